// round 2
// baseline (speedup 1.0000x reference)
#include <cuda_runtime.h>
#include <math.h>

#define L_  192
#define B_  4
#define H_  768
#define NL_ 16
#define LN_EPS 1e-5f

// ---------------- device scratch (no allocs allowed) ----------------
__device__ float g_t [H_ * H_];   // tanh-gate pre-max: t[lb][o], lb = l*4+b
__device__ float g_g [B_ * H_];   // g[b][o] = max_l t
__device__ float g_a [H_ * H_];   // a[lb][o]
__device__ float g_c [H_ * H_];   // c[lb][o]
__device__ float g_dd[B_ * H_];   // d[b][o] + b1[o]

// ---------------- f32x2 packed helpers ----------------
__device__ __forceinline__ unsigned long long pk2(float lo, float hi) {
    unsigned long long r;
    asm("mov.b64 %0, {%1, %2};" : "=l"(r) : "f"(lo), "f"(hi));
    return r;
}
__device__ __forceinline__ void upk2(unsigned long long v, float& lo, float& hi) {
    asm("mov.b64 {%0, %1}, %2;" : "=f"(lo), "=f"(hi) : "l"(v));
}
__device__ __forceinline__ void ffma2(unsigned long long& d,
                                      unsigned long long a, unsigned long long b) {
    asm("fma.rn.f32x2 %0, %1, %2, %3;" : "=l"(d) : "l"(a), "l"(b), "l"(d));
}

// ---------------- generic fp32 tiled GEMM: C[m][n] (+)= sum_k A[m][k]*B[n][k] ----
// M = N = 768, K = 768 fixed. 64x64 block tile, 256 threads, 4x4 per thread.
// flags: bit0 = accumulate into existing C, bit1 = apply tanh(val + bias[n])
#define GF_ACC  1
#define GF_TANH 2

__global__ __launch_bounds__(256)
void gemm_kernel(const float* __restrict__ A, const float* __restrict__ Bm,
                 int ldb, const float* __restrict__ bias,
                 float* __restrict__ C, int flags)
{
    __shared__ float As[16][68];   // As[k][m]
    __shared__ float Bs[16][68];   // Bs[k][n]

    const int tid = threadIdx.x;
    const int tx = tid & 15;       // n sub-tile
    const int ty = tid >> 4;       // m sub-tile
    const int m0 = blockIdx.y * 64;
    const int n0 = blockIdx.x * 64;

    const int lr = tid >> 2;        // 0..63 row within tile (load)
    const int lc = (tid & 3) * 4;   // k group 0,4,8,12 (load)

    const float* Aptr = A  + (size_t)(m0 + lr) * H_ + lc;
    const float* Bptr = Bm + (size_t)(n0 + lr) * ldb + lc;

    unsigned long long acc[4][2];
    #pragma unroll
    for (int i = 0; i < 4; i++) { acc[i][0] = 0ull; acc[i][1] = 0ull; }

    for (int k0 = 0; k0 < H_; k0 += 16) {
        float4 av = *(const float4*)(Aptr + k0);
        float4 bv = *(const float4*)(Bptr + k0);
        __syncthreads();
        As[lc + 0][lr] = av.x; As[lc + 1][lr] = av.y;
        As[lc + 2][lr] = av.z; As[lc + 3][lr] = av.w;
        Bs[lc + 0][lr] = bv.x; Bs[lc + 1][lr] = bv.y;
        Bs[lc + 2][lr] = bv.z; Bs[lc + 3][lr] = bv.w;
        __syncthreads();
        #pragma unroll
        for (int k = 0; k < 16; k++) {
            float4 a4 = *(const float4*)&As[k][ty * 4];
            ulonglong2 bb = *(const ulonglong2*)&Bs[k][tx * 4];
            unsigned long long aa;
            aa = pk2(a4.x, a4.x); ffma2(acc[0][0], aa, bb.x); ffma2(acc[0][1], aa, bb.y);
            aa = pk2(a4.y, a4.y); ffma2(acc[1][0], aa, bb.x); ffma2(acc[1][1], aa, bb.y);
            aa = pk2(a4.z, a4.z); ffma2(acc[2][0], aa, bb.x); ffma2(acc[2][1], aa, bb.y);
            aa = pk2(a4.w, a4.w); ffma2(acc[3][0], aa, bb.x); ffma2(acc[3][1], aa, bb.y);
        }
    }

    const int n = n0 + tx * 4;
    #pragma unroll
    for (int r = 0; r < 4; r++) {
        int m = m0 + ty * 4 + r;
        float4 res;
        upk2(acc[r][0], res.x, res.y);
        upk2(acc[r][1], res.z, res.w);
        float* cp = C + (size_t)m * H_ + n;
        if (flags & GF_ACC) {
            float4 old = *(const float4*)cp;
            res.x += old.x; res.y += old.y; res.z += old.z; res.w += old.w;
        }
        if (flags & GF_TANH) {
            res.x = tanhf(res.x + bias[n + 0]);
            res.y = tanhf(res.y + bias[n + 1]);
            res.z = tanhf(res.z + bias[n + 2]);
            res.w = tanhf(res.w + bias[n + 3]);
        }
        *(float4*)cp = res;
    }
}

// ---------------- max over l: g[b][o] = max_l t[l*4+b][o] ----------------
__global__ __launch_bounds__(256)
void maxred_kernel()
{
    int idx = blockIdx.x * 256 + threadIdx.x;   // 0..3071
    if (idx >= B_ * H_) return;
    int o = idx % H_, b = idx / H_;
    float m = -2.0f;
    #pragma unroll 4
    for (int l = 0; l < L_; l++)
        m = fmaxf(m, g_t[(size_t)(l * B_ + b) * H_ + o]);
    g_g[b * H_ + o] = m;
}

// ---------------- dd[b][o] = sum_h g[b][h] * W1[o][2H+h] + b1[o] ----------------
__global__ __launch_bounds__(256)
void dd_kernel(const float* __restrict__ W1, const float* __restrict__ b1)
{
    int w = (blockIdx.x * blockDim.x + threadIdx.x) >> 5;   // warp id, 0..3071
    int lane = threadIdx.x & 31;
    if (w >= B_ * H_) return;
    int o = w % H_, b = w / H_;
    const float* wrow = W1 + (size_t)o * (3 * H_) + 2 * H_;
    const float* grow = g_g + b * H_;
    float s = 0.f;
    #pragma unroll
    for (int h = lane * 4; h < H_; h += 128) {
        float4 wv = *(const float4*)(wrow + h);
        float4 gv = *(const float4*)(grow + h);
        s += wv.x * gv.x + wv.y * gv.y + wv.z * gv.z + wv.w * gv.w;
    }
    #pragma unroll
    for (int off = 16; off; off >>= 1)
        s += __shfl_xor_sync(0xffffffffu, s, off);
    if (lane == 0) g_dd[b * H_ + o] = s + b1[o];
}

// ---------------- fused pairwise epilogue ----------------
// grid (12, 12, 4) : (i-tile, j-tile, b). 256 threads; thread = one (i, j) pair.
// shared: Wt transposed [h][16] (48KB) + gamma/beta float2 (6KB) + a/c chunks (2x8.25KB)
#define CHUNK 128
#define CSTR  129   // padded row stride (odd -> conflict-free per-row reads)

__global__ __launch_bounds__(256)
void epilogue_kernel(const float* __restrict__ mask,
                     const float* __restrict__ gamma,
                     const float* __restrict__ beta,
                     const float* __restrict__ Wt,
                     const float* __restrict__ bt,
                     float* __restrict__ out)
{
    extern __shared__ float sh[];
    float* s_wt = sh;                       // H_*NL_  = 12288 floats
    float* s_gb = s_wt + H_ * NL_;          // H_*2    =  1536 floats
    float* s_a  = s_gb + H_ * 2;            // 16*CSTR =  2064 floats
    float* s_c  = s_a + 16 * CSTR;          // 16*CSTR

    const int tid = threadIdx.x;
    const int b  = blockIdx.z;
    const int i0 = blockIdx.x * 16;
    const int j0 = blockIdx.y * 16;
    const int ti = tid >> 4, tj = tid & 15;
    const int i = i0 + ti, j = j0 + tj;
    float* outp = out + ((size_t)(i * L_ + j) * B_ + b) * NL_;

    if (i0 > j0) {          // whole tile strictly below diagonal -> zeros
        float4 z = make_float4(0.f, 0.f, 0.f, 0.f);
        float4* op4 = (float4*)outp;
        op4[0] = z; op4[1] = z; op4[2] = z; op4[3] = z;
        return;
    }

    // stage Wt (transposed) + gamma/beta
    for (int idx = tid; idx < H_ * NL_; idx += 256) {
        int n = idx / H_, h = idx - n * H_;
        s_wt[h * NL_ + n] = Wt[idx];
    }
    for (int h = tid; h < H_; h += 256) {
        s_gb[2 * h]     = gamma[h];
        s_gb[2 * h + 1] = beta[h];
    }

    const int lr = tid >> 4;            // row 0..15 (chunk load)
    const int lq = tid & 15;            // 8-float group
    const float* pa_base = g_a + (size_t)((i0 + lr) * B_ + b) * H_;
    const float* pc_base = g_c + (size_t)((j0 + lr) * B_ + b) * H_;
    const float* pd_base = g_dd + b * H_;

    // ---- pass 1: mean / var per pair (thread-local, no reductions) ----
    float sum = 0.f, sumsq = 0.f;
    for (int ck = 0; ck < H_ / CHUNK; ck++) {
        int hb = ck * CHUNK + lq * 8;
        float4 a0 = *(const float4*)(pa_base + hb);
        float4 a1 = *(const float4*)(pa_base + hb + 4);
        float4 d0 = *(const float4*)(pd_base + hb);
        float4 d1 = *(const float4*)(pd_base + hb + 4);
        float4 c0 = *(const float4*)(pc_base + hb);
        float4 c1 = *(const float4*)(pc_base + hb + 4);
        __syncthreads();
        float* sa = &s_a[lr * CSTR + lq * 8];
        float* sc = &s_c[lr * CSTR + lq * 8];
        sa[0] = a0.x + d0.x; sa[1] = a0.y + d0.y; sa[2] = a0.z + d0.z; sa[3] = a0.w + d0.w;
        sa[4] = a1.x + d1.x; sa[5] = a1.y + d1.y; sa[6] = a1.z + d1.z; sa[7] = a1.w + d1.w;
        sc[0] = c0.x; sc[1] = c0.y; sc[2] = c0.z; sc[3] = c0.w;
        sc[4] = c1.x; sc[5] = c1.y; sc[6] = c1.z; sc[7] = c1.w;
        __syncthreads();
        const float* ra = &s_a[ti * CSTR];
        const float* rc = &s_c[tj * CSTR];
        #pragma unroll 8
        for (int hc = 0; hc < CHUNK; hc++) {
            float pre = ra[hc] + rc[hc];
            sum  += pre;
            sumsq = fmaf(pre, pre, sumsq);
        }
    }
    const float inv = 1.0f / (float)H_;
    float mu   = sum * inv;
    float var  = fmaf(-mu, mu, sumsq * inv);
    float rstd = rsqrtf(var + LN_EPS);

    // ---- pass 2: normalize -> elu -> 16-label projection (packed f32x2) ----
    unsigned long long acc[8];
    #pragma unroll
    for (int k = 0; k < 8; k++) acc[k] = 0ull;

    for (int ck = 0; ck < H_ / CHUNK; ck++) {
        int hb = ck * CHUNK + lq * 8;
        float4 a0 = *(const float4*)(pa_base + hb);
        float4 a1 = *(const float4*)(pa_base + hb + 4);
        float4 d0 = *(const float4*)(pd_base + hb);
        float4 d1 = *(const float4*)(pd_base + hb + 4);
        float4 c0 = *(const float4*)(pc_base + hb);
        float4 c1 = *(const float4*)(pc_base + hb + 4);
        __syncthreads();
        float* sa = &s_a[lr * CSTR + lq * 8];
        float* sc = &s_c[lr * CSTR + lq * 8];
        sa[0] = a0.x + d0.x; sa[1] = a0.y + d0.y; sa[2] = a0.z + d0.z; sa[3] = a0.w + d0.w;
        sa[4] = a1.x + d1.x; sa[5] = a1.y + d1.y; sa[6] = a1.z + d1.z; sa[7] = a1.w + d1.w;
        sc[0] = c0.x; sc[1] = c0.y; sc[2] = c0.z; sc[3] = c0.w;
        sc[4] = c1.x; sc[5] = c1.y; sc[6] = c1.z; sc[7] = c1.w;
        __syncthreads();
        const float* ra = &s_a[ti * CSTR];
        const float* rc = &s_c[tj * CSTR];
        #pragma unroll 4
        for (int hc = 0; hc < CHUNK; hc++) {
            int h = ck * CHUNK + hc;
            float pre = ra[hc] + rc[hc];
            float2 gb = *(const float2*)&s_gb[2 * h];
            float x = (pre - mu) * rstd;
            x = fmaf(x, gb.x, gb.y);
            x = (x > 0.f) ? x : (__expf(x) - 1.f);
            unsigned long long xx = pk2(x, x);
            const ulonglong2* wp = (const ulonglong2*)&s_wt[h * NL_];
            ffma2(acc[0], xx, wp[0].x); ffma2(acc[1], xx, wp[0].y);
            ffma2(acc[2], xx, wp[1].x); ffma2(acc[3], xx, wp[1].y);
            ffma2(acc[4], xx, wp[2].x); ffma2(acc[5], xx, wp[2].y);
            ffma2(acc[6], xx, wp[3].x); ffma2(acc[7], xx, wp[3].y);
        }
    }

    float mval = (i <= j) ? mask[i * B_ + b] * mask[j * B_ + b] : 0.f;
    float res[16];
    #pragma unroll
    for (int k = 0; k < 8; k++) upk2(acc[k], res[2 * k], res[2 * k + 1]);
    #pragma unroll
    for (int n = 0; n < 16; n++) {
        float z = res[n] + bt[n];
        res[n] = mval * (1.0f / (1.0f + __expf(-z)));
    }
    float4* op4 = (float4*)outp;
    op4[0] = make_float4(res[0],  res[1],  res[2],  res[3]);
    op4[1] = make_float4(res[4],  res[5],  res[6],  res[7]);
    op4[2] = make_float4(res[8],  res[9],  res[10], res[11]);
    op4[3] = make_float4(res[12], res[13], res[14], res[15]);
}

// ---------------- launch ----------------
extern "C" void kernel_launch(void* const* d_in, const int* in_sizes, int n_in,
                              void* d_out, int out_size)
{
    const float* h_ner   = (const float*)d_in[0];
    const float* h_share = (const float*)d_in[1];
    const float* mask    = (const float*)d_in[2];
    const float* Wn      = (const float*)d_in[3];
    const float* bn      = (const float*)d_in[4];
    const float* W1      = (const float*)d_in[5];
    const float* b1      = (const float*)d_in[6];
    const float* gamma   = (const float*)d_in[7];
    const float* beta    = (const float*)d_in[8];
    const float* Wt      = (const float*)d_in[9];
    const float* bt      = (const float*)d_in[10];
    float* out = (float*)d_out;

    float *t_p, *g_p, *a_p, *c_p, *dd_p;
    cudaGetSymbolAddress((void**)&t_p,  g_t);
    cudaGetSymbolAddress((void**)&g_p,  g_g);
    cudaGetSymbolAddress((void**)&a_p,  g_a);
    cudaGetSymbolAddress((void**)&c_p,  g_c);
    cudaGetSymbolAddress((void**)&dd_p, g_dd);
    (void)g_p; (void)dd_p; (void)in_sizes; (void)n_in; (void)out_size;

    dim3 gg(12, 12);
    // gate GEMM: t = tanh(h_share @ Wn_s^T + h_ner @ Wn_r^T + bn)
    gemm_kernel<<<gg, 256>>>(h_share, Wn,        2 * H_, nullptr, t_p, 0);
    gemm_kernel<<<gg, 256>>>(h_ner,   Wn + H_,   2 * H_, bn,      t_p, GF_ACC | GF_TANH);
    maxred_kernel<<<12, 256>>>();
    // a = h_ner @ W_st^T ; c = h_ner @ W_en^T
    gemm_kernel<<<gg, 256>>>(h_ner,   W1,        3 * H_, nullptr, a_p, 0);
    gemm_kernel<<<gg, 256>>>(h_ner,   W1 + H_,   3 * H_, nullptr, c_p, 0);
    dd_kernel<<<384, 256>>>(W1, b1);

    const int smem_epi = (H_ * NL_ + H_ * 2 + 2 * 16 * CSTR) * (int)sizeof(float); // 71808
    cudaFuncSetAttribute(epilogue_kernel,
                         cudaFuncAttributeMaxDynamicSharedMemorySize, smem_epi);
    epilogue_kernel<<<dim3(12, 12, 4), 256, smem_epi>>>(mask, gamma, beta, Wt, bt, out);
}

// round 3
// speedup vs baseline: 1.0609x; 1.0609x over previous
#include <cuda_runtime.h>
#include <math.h>

#define L_  192
#define B_  4
#define H_  768
#define NL_ 16
#define LN_EPS 1e-5f

// ---------------- device scratch ----------------
__device__ float g_t [H_ * H_];        // tanh-gate pre-max: t[lb][o]
__device__ float g_g [B_ * H_];        // g[b][o]
__device__ float g_a [H_ * H_];        // a[lb][o]
__device__ float g_c [H_ * H_];        // c[lb][o]
__device__ float g_dd[B_ * H_];        // d[b][o] + b1[o]
__device__ float g_S [2][B_][L_];      // row sums of a (0) / c (1)
__device__ float g_Q [2][B_][L_];      // row sum-of-squares
__device__ float g_X [2][B_][L_];      // row dot with dd
__device__ float g_Sdd[B_], g_Qdd[B_];
__device__ float g_U [B_][L_][L_];     // U[b][i][j] = sum_h a_ih * c_jh

// ---------------- f32x2 packed helpers ----------------
__device__ __forceinline__ unsigned long long pk2(float lo, float hi) {
    unsigned long long r;
    asm("mov.b64 %0, {%1, %2};" : "=l"(r) : "f"(lo), "f"(hi));
    return r;
}
__device__ __forceinline__ void upk2(unsigned long long v, float& lo, float& hi) {
    asm("mov.b64 {%0, %1}, %2;" : "=f"(lo), "=f"(hi) : "l"(v));
}
__device__ __forceinline__ void ffma2(unsigned long long& d,
                                      unsigned long long a, unsigned long long b) {
    asm("fma.rn.f32x2 %0, %1, %2, %3;" : "=l"(d) : "l"(a), "l"(b), "l"(d));
}

// ---------------- shared 64x64 tile MAC over K=768 ----------------
// Aptr/Bptr already offset to (row m0+lr / n0+lr, col lc); k advances contiguously.
__device__ __forceinline__ void mac_768(
    const float* __restrict__ Aptr, const float* __restrict__ Bptr,
    float (*As)[68], float (*Bs)[68],
    int lr, int lc, int tx, int ty,
    unsigned long long acc[4][2])
{
    float4 av = *(const float4*)(Aptr);
    float4 bv = *(const float4*)(Bptr);
    for (int k0 = 0; k0 < H_; k0 += 16) {
        __syncthreads();
        As[lc + 0][lr] = av.x; As[lc + 1][lr] = av.y;
        As[lc + 2][lr] = av.z; As[lc + 3][lr] = av.w;
        Bs[lc + 0][lr] = bv.x; Bs[lc + 1][lr] = bv.y;
        Bs[lc + 2][lr] = bv.z; Bs[lc + 3][lr] = bv.w;
        __syncthreads();
        if (k0 + 16 < H_) {
            av = *(const float4*)(Aptr + k0 + 16);
            bv = *(const float4*)(Bptr + k0 + 16);
        }
        #pragma unroll
        for (int k = 0; k < 16; k++) {
            float4 a4 = *(const float4*)&As[k][ty * 4];
            ulonglong2 bb = *(const ulonglong2*)&Bs[k][tx * 4];
            unsigned long long aa;
            aa = pk2(a4.x, a4.x); ffma2(acc[0][0], aa, bb.x); ffma2(acc[0][1], aa, bb.y);
            aa = pk2(a4.y, a4.y); ffma2(acc[1][0], aa, bb.x); ffma2(acc[1][1], aa, bb.y);
            aa = pk2(a4.z, a4.z); ffma2(acc[2][0], aa, bb.x); ffma2(acc[2][1], aa, bb.y);
            aa = pk2(a4.w, a4.w); ffma2(acc[3][0], aa, bb.x); ffma2(acc[3][1], aa, bb.y);
        }
    }
}

// ---------------- fused 3-way GEMM: z=0 -> t (2 phases + tanh), z=1 -> a, z=2 -> c
__global__ __launch_bounds__(256)
void gemm3_kernel(const float* __restrict__ h_ner, const float* __restrict__ h_share,
                  const float* __restrict__ Wn, const float* __restrict__ bn,
                  const float* __restrict__ W1)
{
    __shared__ float As[16][68];
    __shared__ float Bs[16][68];

    const int tid = threadIdx.x;
    const int tx = tid & 15, ty = tid >> 4;
    const int lr = tid >> 2, lc = (tid & 3) * 4;
    const int m0 = blockIdx.y * 64, n0 = blockIdx.x * 64;
    const int z  = blockIdx.z;

    unsigned long long acc[4][2];
    #pragma unroll
    for (int i = 0; i < 4; i++) { acc[i][0] = 0ull; acc[i][1] = 0ull; }

    float* C;
    if (z == 0) {
        mac_768(h_share + (size_t)(m0 + lr) * H_ + lc,
                Wn      + (size_t)(n0 + lr) * (2 * H_) + lc,
                As, Bs, lr, lc, tx, ty, acc);
        mac_768(h_ner   + (size_t)(m0 + lr) * H_ + lc,
                Wn + H_ + (size_t)(n0 + lr) * (2 * H_) + lc,
                As, Bs, lr, lc, tx, ty, acc);
        C = g_t;
    } else if (z == 1) {
        mac_768(h_ner   + (size_t)(m0 + lr) * H_ + lc,
                W1      + (size_t)(n0 + lr) * (3 * H_) + lc,
                As, Bs, lr, lc, tx, ty, acc);
        C = g_a;
    } else {
        mac_768(h_ner   + (size_t)(m0 + lr) * H_ + lc,
                W1 + H_ + (size_t)(n0 + lr) * (3 * H_) + lc,
                As, Bs, lr, lc, tx, ty, acc);
        C = g_c;
    }

    const int n = n0 + tx * 4;
    #pragma unroll
    for (int r = 0; r < 4; r++) {
        int m = m0 + ty * 4 + r;
        float4 res;
        upk2(acc[r][0], res.x, res.y);
        upk2(acc[r][1], res.z, res.w);
        if (z == 0) {
            res.x = tanhf(res.x + bn[n + 0]);
            res.y = tanhf(res.y + bn[n + 1]);
            res.z = tanhf(res.z + bn[n + 2]);
            res.w = tanhf(res.w + bn[n + 3]);
        }
        *(float4*)(C + (size_t)m * H_ + n) = res;
    }
}

// ---------------- U[b][i][j] = sum_h a_ih c_jh ----------------
__global__ __launch_bounds__(256)
void ugemm_kernel()
{
    __shared__ float As[16][68];
    __shared__ float Bs[16][68];
    const int tid = threadIdx.x;
    const int tx = tid & 15, ty = tid >> 4;
    const int lr = tid >> 2, lc = (tid & 3) * 4;
    const int m0 = blockIdx.y * 64, n0 = blockIdx.x * 64;
    const int b  = blockIdx.z;

    unsigned long long acc[4][2];
    #pragma unroll
    for (int i = 0; i < 4; i++) { acc[i][0] = 0ull; acc[i][1] = 0ull; }

    mac_768(g_a + (size_t)((m0 + lr) * B_ + b) * H_ + lc,
            g_c + (size_t)((n0 + lr) * B_ + b) * H_ + lc,
            As, Bs, lr, lc, tx, ty, acc);

    const int n = n0 + tx * 4;
    #pragma unroll
    for (int r = 0; r < 4; r++) {
        int m = m0 + ty * 4 + r;
        float4 res;
        upk2(acc[r][0], res.x, res.y);
        upk2(acc[r][1], res.z, res.w);
        *(float4*)(&g_U[b][m][n]) = res;
    }
}

// ---------------- max over l ----------------
__global__ __launch_bounds__(256)
void maxred_kernel()
{
    int idx = blockIdx.x * 256 + threadIdx.x;
    if (idx >= B_ * H_) return;
    int o = idx % H_, b = idx / H_;
    float m = -2.0f;
    #pragma unroll 4
    for (int l = 0; l < L_; l++)
        m = fmaxf(m, g_t[(size_t)(l * B_ + b) * H_ + o]);
    g_g[b * H_ + o] = m;
}

// ---------------- dd[b][o] = g[b] . W1[o][2H:] + b1[o] ----------------
__global__ __launch_bounds__(256)
void dd_kernel(const float* __restrict__ W1, const float* __restrict__ b1)
{
    int w = (blockIdx.x * blockDim.x + threadIdx.x) >> 5;
    int lane = threadIdx.x & 31;
    if (w >= B_ * H_) return;
    int o = w % H_, b = w / H_;
    const float* wrow = W1 + (size_t)o * (3 * H_) + 2 * H_;
    const float* grow = g_g + b * H_;
    float s = 0.f;
    #pragma unroll
    for (int h = lane * 4; h < H_; h += 128) {
        float4 wv = *(const float4*)(wrow + h);
        float4 gv = *(const float4*)(grow + h);
        s += wv.x * gv.x + wv.y * gv.y + wv.z * gv.z + wv.w * gv.w;
    }
    #pragma unroll
    for (int off = 16; off; off >>= 1)
        s += __shfl_xor_sync(0xffffffffu, s, off);
    if (lane == 0) g_dd[b * H_ + o] = s + b1[o];
}

// ---------------- per-row stats: S, Q, X(=dot with dd); plus dd stats ----------------
__global__ __launch_bounds__(256)
void stats_kernel()
{
    const int lane = threadIdx.x & 31;
    const int sub  = threadIdx.x >> 5;
    if (blockIdx.x < L_) {
        const int r = blockIdx.x;
        const int b = sub >> 1, kind = sub & 1;
        const float* row = (kind ? g_c : g_a) + (size_t)(r * B_ + b) * H_;
        const float* dd  = g_dd + b * H_;
        float s = 0.f, q = 0.f, x = 0.f;
        #pragma unroll
        for (int h = lane * 4; h < H_; h += 128) {
            float4 v = *(const float4*)(row + h);
            float4 d = *(const float4*)(dd + h);
            s += v.x + v.y + v.z + v.w;
            q = fmaf(v.x, v.x, fmaf(v.y, v.y, fmaf(v.z, v.z, fmaf(v.w, v.w, q))));
            x = fmaf(v.x, d.x, fmaf(v.y, d.y, fmaf(v.z, d.z, fmaf(v.w, d.w, x))));
        }
        #pragma unroll
        for (int off = 16; off; off >>= 1) {
            s += __shfl_xor_sync(0xffffffffu, s, off);
            q += __shfl_xor_sync(0xffffffffu, q, off);
            x += __shfl_xor_sync(0xffffffffu, x, off);
        }
        if (lane == 0) {
            g_S[kind][b][r] = s;
            g_Q[kind][b][r] = q;
            g_X[kind][b][r] = x;
        }
    } else if (sub < B_) {
        const int b = sub;
        const float* dd = g_dd + b * H_;
        float s = 0.f, q = 0.f;
        #pragma unroll
        for (int h = lane * 4; h < H_; h += 128) {
            float4 d = *(const float4*)(dd + h);
            s += d.x + d.y + d.z + d.w;
            q = fmaf(d.x, d.x, fmaf(d.y, d.y, fmaf(d.z, d.z, fmaf(d.w, d.w, q))));
        }
        #pragma unroll
        for (int off = 16; off; off >>= 1) {
            s += __shfl_xor_sync(0xffffffffu, s, off);
            q += __shfl_xor_sync(0xffffffffu, q, off);
        }
        if (lane == 0) { g_Sdd[b] = s; g_Qdd[b] = q; }
    }
}

// ---------------- fused single-pass pairwise epilogue ----------------
#define CHUNK 128
#define CSTR  130   // even stride: 8B-aligned float2 rows, banks still distinct

__global__ __launch_bounds__(256)
void epilogue_kernel(const float* __restrict__ mask,
                     const float* __restrict__ gamma,
                     const float* __restrict__ beta,
                     const float* __restrict__ Wt,
                     const float* __restrict__ bt,
                     float* __restrict__ out)
{
    extern __shared__ float sh[];
    float* s_wt = sh;                       // H_*NL_ floats
    float* s_gb = s_wt + H_ * NL_;          // H_*2
    float* s_a  = s_gb + H_ * 2;            // 16*CSTR
    float* s_c  = s_a + 16 * CSTR;          // 16*CSTR

    const int tid = threadIdx.x;
    const int b  = blockIdx.z;
    const int i0 = blockIdx.x * 16;
    const int j0 = blockIdx.y * 16;
    const int ti = tid >> 4, tj = tid & 15;
    const int i = i0 + ti, j = j0 + tj;
    float* outp = out + ((size_t)(i * L_ + j) * B_ + b) * NL_;

    if (i0 > j0) {
        float4 z = make_float4(0.f, 0.f, 0.f, 0.f);
        float4* op4 = (float4*)outp;
        op4[0] = z; op4[1] = z; op4[2] = z; op4[3] = z;
        return;
    }

    // stage Wt (transposed) + gamma/beta
    for (int idx = tid; idx < H_ * NL_; idx += 256) {
        int n = idx / H_, h = idx - n * H_;
        s_wt[h * NL_ + n] = Wt[idx];
    }
    for (int h = tid; h < H_; h += 256) {
        s_gb[2 * h]     = gamma[h];
        s_gb[2 * h + 1] = beta[h];
    }

    // per-pair LN stats from precomputed moments
    const float inv = 1.0f / (float)H_;
    float mu, rstd;
    {
        float S0 = g_S[0][b][i], Q0 = g_Q[0][b][i], X0 = g_X[0][b][i];
        float S1 = g_S[1][b][j], Q1 = g_Q[1][b][j], X1 = g_X[1][b][j];
        float Uv = g_U[b][i][j];
        float sum   = S0 + S1 + g_Sdd[b];
        float sumsq = Q0 + Q1 + g_Qdd[b] + 2.0f * (Uv + X0 + X1);
        mu = sum * inv;
        float var = fmaf(-mu, mu, sumsq * inv);
        rstd = rsqrtf(var + LN_EPS);
    }

    const int lr = tid >> 4;            // staging row
    const int lq = tid & 15;            // staging 8-float group
    const float* pa_base = g_a + (size_t)((i0 + lr) * B_ + b) * H_;
    const float* pc_base = g_c + (size_t)((j0 + lr) * B_ + b) * H_;
    const float* pd_base = g_dd + b * H_;

    unsigned long long acc[8];
    #pragma unroll
    for (int k = 0; k < 8; k++) acc[k] = 0ull;

    for (int ck = 0; ck < H_ / CHUNK; ck++) {
        int hb = ck * CHUNK + lq * 8;
        float4 a0 = *(const float4*)(pa_base + hb);
        float4 a1 = *(const float4*)(pa_base + hb + 4);
        float4 d0 = *(const float4*)(pd_base + hb);
        float4 d1 = *(const float4*)(pd_base + hb + 4);
        float4 c0 = *(const float4*)(pc_base + hb);
        float4 c1 = *(const float4*)(pc_base + hb + 4);
        __syncthreads();
        float* sa = &s_a[lr * CSTR + lq * 8];
        float* sc = &s_c[lr * CSTR + lq * 8];
        sa[0] = a0.x + d0.x; sa[1] = a0.y + d0.y; sa[2] = a0.z + d0.z; sa[3] = a0.w + d0.w;
        sa[4] = a1.x + d1.x; sa[5] = a1.y + d1.y; sa[6] = a1.z + d1.z; sa[7] = a1.w + d1.w;
        sc[0] = c0.x; sc[1] = c0.y; sc[2] = c0.z; sc[3] = c0.w;
        sc[4] = c1.x; sc[5] = c1.y; sc[6] = c1.z; sc[7] = c1.w;
        __syncthreads();
        const float* ra = &s_a[ti * CSTR];
        const float* rc = &s_c[tj * CSTR];
        #pragma unroll 4
        for (int hc = 0; hc < CHUNK; hc += 2) {
            int h = ck * CHUNK + hc;
            float2 pa = *(const float2*)&ra[hc];
            float2 pc = *(const float2*)&rc[hc];
            float4 gb = *(const float4*)&s_gb[2 * h];
            float x0 = fmaf((pa.x + pc.x - mu) * rstd, gb.x, gb.y);
            float x1 = fmaf((pa.y + pc.y - mu) * rstd, gb.z, gb.w);
            x0 = (x0 > 0.f) ? x0 : (__expf(x0) - 1.f);
            x1 = (x1 > 0.f) ? x1 : (__expf(x1) - 1.f);
            unsigned long long xx0 = pk2(x0, x0);
            unsigned long long xx1 = pk2(x1, x1);
            const ulonglong2* wp0 = (const ulonglong2*)&s_wt[h * NL_];
            const ulonglong2* wp1 = (const ulonglong2*)&s_wt[(h + 1) * NL_];
            ffma2(acc[0], xx0, wp0[0].x); ffma2(acc[1], xx0, wp0[0].y);
            ffma2(acc[2], xx0, wp0[1].x); ffma2(acc[3], xx0, wp0[1].y);
            ffma2(acc[4], xx0, wp0[2].x); ffma2(acc[5], xx0, wp0[2].y);
            ffma2(acc[6], xx0, wp0[3].x); ffma2(acc[7], xx0, wp0[3].y);
            ffma2(acc[0], xx1, wp1[0].x); ffma2(acc[1], xx1, wp1[0].y);
            ffma2(acc[2], xx1, wp1[1].x); ffma2(acc[3], xx1, wp1[1].y);
            ffma2(acc[4], xx1, wp1[2].x); ffma2(acc[5], xx1, wp1[2].y);
            ffma2(acc[6], xx1, wp1[3].x); ffma2(acc[7], xx1, wp1[3].y);
        }
    }

    float mval = (i <= j) ? mask[i * B_ + b] * mask[j * B_ + b] : 0.f;
    float res[16];
    #pragma unroll
    for (int k = 0; k < 8; k++) upk2(acc[k], res[2 * k], res[2 * k + 1]);
    #pragma unroll
    for (int n = 0; n < 16; n++) {
        float z = res[n] + bt[n];
        res[n] = mval * (1.0f / (1.0f + __expf(-z)));
    }
    float4* op4 = (float4*)outp;
    op4[0] = make_float4(res[0],  res[1],  res[2],  res[3]);
    op4[1] = make_float4(res[4],  res[5],  res[6],  res[7]);
    op4[2] = make_float4(res[8],  res[9],  res[10], res[11]);
    op4[3] = make_float4(res[12], res[13], res[14], res[15]);
}

// ---------------- launch ----------------
extern "C" void kernel_launch(void* const* d_in, const int* in_sizes, int n_in,
                              void* d_out, int out_size)
{
    const float* h_ner   = (const float*)d_in[0];
    const float* h_share = (const float*)d_in[1];
    const float* mask    = (const float*)d_in[2];
    const float* Wn      = (const float*)d_in[3];
    const float* bn      = (const float*)d_in[4];
    const float* W1      = (const float*)d_in[5];
    const float* b1      = (const float*)d_in[6];
    const float* gamma   = (const float*)d_in[7];
    const float* beta    = (const float*)d_in[8];
    const float* Wt      = (const float*)d_in[9];
    const float* bt      = (const float*)d_in[10];
    float* out = (float*)d_out;
    (void)in_sizes; (void)n_in; (void)out_size;

    gemm3_kernel<<<dim3(12, 12, 3), 256>>>(h_ner, h_share, Wn, bn, W1);
    maxred_kernel<<<12, 256>>>();
    dd_kernel<<<384, 256>>>(W1, b1);
    stats_kernel<<<L_ + 1, 256>>>();
    ugemm_kernel<<<dim3(3, 3, 4), 256>>>();

    const int smem_epi = (H_ * NL_ + H_ * 2 + 2 * 16 * CSTR) * (int)sizeof(float);
    cudaFuncSetAttribute(epilogue_kernel,
                         cudaFuncAttributeMaxDynamicSharedMemorySize, smem_epi);
    epilogue_kernel<<<dim3(12, 12, 4), 256, smem_epi>>>(mask, gamma, beta, Wt, bt, out);
}

// round 15
// speedup vs baseline: 1.3511x; 1.2736x over previous
#include <cuda_runtime.h>
#include <math.h>

#define L_  192
#define B_  4
#define H_  768
#define NL_ 16
#define LN_EPS 1e-5f

// ---------------- device scratch ----------------
__device__ float g_t [H_ * H_];        // gate partial 1: h_share @ Wn_s^T
__device__ float g_t2[H_ * H_];        // gate partial 2: h_ner @ Wn_r^T
__device__ float g_g [B_ * H_];        // g[b][o] = tanh(max_l(t1+t2) + bn)
__device__ float g_a [H_ * H_];        // a[lb][o]
__device__ float g_c [H_ * H_];        // c[lb][o]
__device__ float g_dd[B_ * H_];        // d[b][o] + b1[o]
__device__ float g_S [2][B_][L_];      // row sums of a(0)/c(1)
__device__ float g_Q [2][B_][L_];      // row sum-of-squares
__device__ float g_X [2][B_][L_];      // row dot with dd
__device__ float g_Sdd[B_], g_Qdd[B_];
__device__ float g_U0[B_][L_][L_];     // U partial (k 0..383)
__device__ float g_U1[B_][L_][L_];     // U partial (k 384..767)

// ---------------- f32x2 packed helpers ----------------
__device__ __forceinline__ unsigned long long pk2(float lo, float hi) {
    unsigned long long r;
    asm("mov.b64 %0, {%1, %2};" : "=l"(r) : "f"(lo), "f"(hi));
    return r;
}
__device__ __forceinline__ void upk2(unsigned long long v, float& lo, float& hi) {
    asm("mov.b64 {%0, %1}, %2;" : "=f"(lo), "=f"(hi) : "l"(v));
}
__device__ __forceinline__ void ffma2(unsigned long long& d,
                                      unsigned long long a, unsigned long long b) {
    asm("fma.rn.f32x2 %0, %1, %2, %3;" : "=l"(d) : "l"(a), "l"(b), "l"(d));
}

// ============ main GEMM: 128x128 tile, 8x8 micro, K=768, 4 balanced z-slices ====
__global__ __launch_bounds__(256, 1)
void gemm4_kernel(const float* __restrict__ h_ner, const float* __restrict__ h_share,
                  const float* __restrict__ Wn, const float* __restrict__ W1)
{
    __shared__ float As[16][132];
    __shared__ float Bs[16][132];

    const int tid = threadIdx.x;
    const int tx = tid & 15, ty = tid >> 4;     // micro-tile coords
    const int lr = tid >> 1, lc = (tid & 1) * 8; // staging coords
    const int m0 = blockIdx.y * 128, n0 = blockIdx.x * 128;
    const int z  = blockIdx.z;

    const float* A; const float* Bm; int ldb; float* C;
    if (z == 0)      { A = h_share; Bm = Wn;      ldb = 2 * H_; C = g_t;  }
    else if (z == 1) { A = h_ner;   Bm = Wn + H_; ldb = 2 * H_; C = g_t2; }
    else if (z == 2) { A = h_ner;   Bm = W1;      ldb = 3 * H_; C = g_a;  }
    else             { A = h_ner;   Bm = W1 + H_; ldb = 3 * H_; C = g_c;  }

    const float* Ap = A  + (size_t)(m0 + lr) * H_  + lc;
    const float* Bp = Bm + (size_t)(n0 + lr) * ldb + lc;

    unsigned long long acc[8][4];
    #pragma unroll
    for (int r = 0; r < 8; r++)
        #pragma unroll
        for (int q = 0; q < 4; q++) acc[r][q] = 0ull;

    float4 av0 = *(const float4*)(Ap);
    float4 av1 = *(const float4*)(Ap + 4);
    float4 bv0 = *(const float4*)(Bp);
    float4 bv1 = *(const float4*)(Bp + 4);

    for (int k0 = 0; k0 < H_; k0 += 16) {
        __syncthreads();
        As[lc + 0][lr] = av0.x; As[lc + 1][lr] = av0.y;
        As[lc + 2][lr] = av0.z; As[lc + 3][lr] = av0.w;
        As[lc + 4][lr] = av1.x; As[lc + 5][lr] = av1.y;
        As[lc + 6][lr] = av1.z; As[lc + 7][lr] = av1.w;
        Bs[lc + 0][lr] = bv0.x; Bs[lc + 1][lr] = bv0.y;
        Bs[lc + 2][lr] = bv0.z; Bs[lc + 3][lr] = bv0.w;
        Bs[lc + 4][lr] = bv1.x; Bs[lc + 5][lr] = bv1.y;
        Bs[lc + 6][lr] = bv1.z; Bs[lc + 7][lr] = bv1.w;
        __syncthreads();
        if (k0 + 16 < H_) {
            av0 = *(const float4*)(Ap + k0 + 16);
            av1 = *(const float4*)(Ap + k0 + 20);
            bv0 = *(const float4*)(Bp + k0 + 16);
            bv1 = *(const float4*)(Bp + k0 + 20);
        }
        #pragma unroll
        for (int k = 0; k < 16; k++) {
            float4 am0 = *(const float4*)&As[k][ty * 8];
            float4 am1 = *(const float4*)&As[k][ty * 8 + 4];
            ulonglong2 b0 = *(const ulonglong2*)&Bs[k][tx * 4];
            ulonglong2 b1 = *(const ulonglong2*)&Bs[k][64 + tx * 4];
            unsigned long long aa;
            aa = pk2(am0.x, am0.x); ffma2(acc[0][0], aa, b0.x); ffma2(acc[0][1], aa, b0.y);
                                    ffma2(acc[0][2], aa, b1.x); ffma2(acc[0][3], aa, b1.y);
            aa = pk2(am0.y, am0.y); ffma2(acc[1][0], aa, b0.x); ffma2(acc[1][1], aa, b0.y);
                                    ffma2(acc[1][2], aa, b1.x); ffma2(acc[1][3], aa, b1.y);
            aa = pk2(am0.z, am0.z); ffma2(acc[2][0], aa, b0.x); ffma2(acc[2][1], aa, b0.y);
                                    ffma2(acc[2][2], aa, b1.x); ffma2(acc[2][3], aa, b1.y);
            aa = pk2(am0.w, am0.w); ffma2(acc[3][0], aa, b0.x); ffma2(acc[3][1], aa, b0.y);
                                    ffma2(acc[3][2], aa, b1.x); ffma2(acc[3][3], aa, b1.y);
            aa = pk2(am1.x, am1.x); ffma2(acc[4][0], aa, b0.x); ffma2(acc[4][1], aa, b0.y);
                                    ffma2(acc[4][2], aa, b1.x); ffma2(acc[4][3], aa, b1.y);
            aa = pk2(am1.y, am1.y); ffma2(acc[5][0], aa, b0.x); ffma2(acc[5][1], aa, b0.y);
                                    ffma2(acc[5][2], aa, b1.x); ffma2(acc[5][3], aa, b1.y);
            aa = pk2(am1.z, am1.z); ffma2(acc[6][0], aa, b0.x); ffma2(acc[6][1], aa, b0.y);
                                    ffma2(acc[6][2], aa, b1.x); ffma2(acc[6][3], aa, b1.y);
            aa = pk2(am1.w, am1.w); ffma2(acc[7][0], aa, b0.x); ffma2(acc[7][1], aa, b0.y);
                                    ffma2(acc[7][2], aa, b1.x); ffma2(acc[7][3], aa, b1.y);
        }
    }

    #pragma unroll
    for (int r = 0; r < 8; r++) {
        int m = m0 + ty * 8 + r;
        float4 lo, hi;
        upk2(acc[r][0], lo.x, lo.y); upk2(acc[r][1], lo.z, lo.w);
        upk2(acc[r][2], hi.x, hi.y); upk2(acc[r][3], hi.z, hi.w);
        *(float4*)(C + (size_t)m * H_ + n0 + tx * 4)      = lo;
        *(float4*)(C + (size_t)m * H_ + n0 + 64 + tx * 4) = hi;
    }
}

// ---------------- g[b][o] = tanh(max_l(t1+t2) + bn[o]) ----------------
__global__ __launch_bounds__(256)
void maxred_kernel(const float* __restrict__ bn)
{
    int idx = blockIdx.x * 256 + threadIdx.x;
    if (idx >= B_ * H_) return;
    int o = idx % H_, b = idx / H_;
    float m = -INFINITY;
    #pragma unroll 4
    for (int l = 0; l < L_; l++) {
        size_t p = (size_t)(l * B_ + b) * H_ + o;
        m = fmaxf(m, g_t[p] + g_t2[p]);
    }
    g_g[b * H_ + o] = tanhf(m + bn[o]);
}

// ---------------- dd[b][o] = g[b] . W1[o][2H:] + b1[o] ----------------
__global__ __launch_bounds__(256)
void dd_kernel(const float* __restrict__ W1, const float* __restrict__ b1)
{
    int w = (blockIdx.x * blockDim.x + threadIdx.x) >> 5;
    int lane = threadIdx.x & 31;
    if (w >= B_ * H_) return;
    int o = w % H_, b = w / H_;
    const float* wrow = W1 + (size_t)o * (3 * H_) + 2 * H_;
    const float* grow = g_g + b * H_;
    float s = 0.f;
    #pragma unroll
    for (int h = lane * 4; h < H_; h += 128) {
        float4 wv = *(const float4*)(wrow + h);
        float4 gv = *(const float4*)(grow + h);
        s += wv.x * gv.x + wv.y * gv.y + wv.z * gv.z + wv.w * gv.w;
    }
    #pragma unroll
    for (int off = 16; off; off >>= 1)
        s += __shfl_xor_sync(0xffffffffu, s, off);
    if (lane == 0) g_dd[b * H_ + o] = s + b1[o];
}

// ---------------- per-row stats: S, Q, X(=dot with dd); plus dd stats ----------------
__global__ __launch_bounds__(256)
void stats_kernel()
{
    const int lane = threadIdx.x & 31;
    const int sub  = threadIdx.x >> 5;
    if (blockIdx.x < L_) {
        const int r = blockIdx.x;
        const int b = sub >> 1, kind = sub & 1;
        const float* row = (kind ? g_c : g_a) + (size_t)(r * B_ + b) * H_;
        const float* dd  = g_dd + b * H_;
        float s = 0.f, q = 0.f, x = 0.f;
        #pragma unroll
        for (int h = lane * 4; h < H_; h += 128) {
            float4 v = *(const float4*)(row + h);
            float4 d = *(const float4*)(dd + h);
            s += v.x + v.y + v.z + v.w;
            q = fmaf(v.x, v.x, fmaf(v.y, v.y, fmaf(v.z, v.z, fmaf(v.w, v.w, q))));
            x = fmaf(v.x, d.x, fmaf(v.y, d.y, fmaf(v.z, d.z, fmaf(v.w, d.w, x))));
        }
        #pragma unroll
        for (int off = 16; off; off >>= 1) {
            s += __shfl_xor_sync(0xffffffffu, s, off);
            q += __shfl_xor_sync(0xffffffffu, q, off);
            x += __shfl_xor_sync(0xffffffffu, x, off);
        }
        if (lane == 0) {
            g_S[kind][b][r] = s;
            g_Q[kind][b][r] = q;
            g_X[kind][b][r] = x;
        }
    } else if (sub < B_) {
        const int b = sub;
        const float* dd = g_dd + b * H_;
        float s = 0.f, q = 0.f;
        #pragma unroll
        for (int h = lane * 4; h < H_; h += 128) {
            float4 d = *(const float4*)(dd + h);
            s += d.x + d.y + d.z + d.w;
            q = fmaf(d.x, d.x, fmaf(d.y, d.y, fmaf(d.z, d.z, fmaf(d.w, d.w, q))));
        }
        #pragma unroll
        for (int off = 16; off; off >>= 1) {
            s += __shfl_xor_sync(0xffffffffu, s, off);
            q += __shfl_xor_sync(0xffffffffu, q, off);
        }
        if (lane == 0) { g_Sdd[b] = s; g_Qdd[b] = q; }
    }
}

// ---------------- U[b][i][j] = sum_h a_ih c_jh (K split in 2) ----------------
__global__ __launch_bounds__(256)
void ugemm_kernel()
{
    __shared__ float As[16][68];
    __shared__ float Bs[16][68];
    const int tid = threadIdx.x;
    const int tx = tid & 15, ty = tid >> 4;
    const int lr = tid >> 2, lc = (tid & 3) * 4;
    const int m0 = blockIdx.y * 64, n0 = blockIdx.x * 64;
    const int b    = blockIdx.z >> 1;
    const int half = blockIdx.z & 1;
    const int koff = half * 384;

    unsigned long long acc[4][2];
    #pragma unroll
    for (int i = 0; i < 4; i++) { acc[i][0] = 0ull; acc[i][1] = 0ull; }

    const float* Ap = g_a + (size_t)((m0 + lr) * B_ + b) * H_ + koff + lc;
    const float* Bp = g_c + (size_t)((n0 + lr) * B_ + b) * H_ + koff + lc;

    float4 av = *(const float4*)(Ap);
    float4 bv = *(const float4*)(Bp);
    for (int k0 = 0; k0 < 384; k0 += 16) {
        __syncthreads();
        As[lc + 0][lr] = av.x; As[lc + 1][lr] = av.y;
        As[lc + 2][lr] = av.z; As[lc + 3][lr] = av.w;
        Bs[lc + 0][lr] = bv.x; Bs[lc + 1][lr] = bv.y;
        Bs[lc + 2][lr] = bv.z; Bs[lc + 3][lr] = bv.w;
        __syncthreads();
        if (k0 + 16 < 384) {
            av = *(const float4*)(Ap + k0 + 16);
            bv = *(const float4*)(Bp + k0 + 16);
        }
        #pragma unroll
        for (int k = 0; k < 16; k++) {
            float4 a4 = *(const float4*)&As[k][ty * 4];
            ulonglong2 bb = *(const ulonglong2*)&Bs[k][tx * 4];
            unsigned long long aa;
            aa = pk2(a4.x, a4.x); ffma2(acc[0][0], aa, bb.x); ffma2(acc[0][1], aa, bb.y);
            aa = pk2(a4.y, a4.y); ffma2(acc[1][0], aa, bb.x); ffma2(acc[1][1], aa, bb.y);
            aa = pk2(a4.z, a4.z); ffma2(acc[2][0], aa, bb.x); ffma2(acc[2][1], aa, bb.y);
            aa = pk2(a4.w, a4.w); ffma2(acc[3][0], aa, bb.x); ffma2(acc[3][1], aa, bb.y);
        }
    }

    float* U = half ? &g_U1[b][0][0] : &g_U0[b][0][0];
    const int n = n0 + tx * 4;
    #pragma unroll
    for (int r = 0; r < 4; r++) {
        int m = m0 + ty * 4 + r;
        float4 res;
        upk2(acc[r][0], res.x, res.y);
        upk2(acc[r][1], res.z, res.w);
        *(float4*)(U + (size_t)m * L_ + n) = res;
    }
}

// ---------------- fused single-pass pairwise epilogue ----------------
#define CHUNK 128
#define CSTR  130

__global__ __launch_bounds__(256)
void epilogue_kernel(const float* __restrict__ mask,
                     const float* __restrict__ gamma,
                     const float* __restrict__ beta,
                     const float* __restrict__ Wt,
                     const float* __restrict__ bt,
                     float* __restrict__ out)
{
    extern __shared__ float sh[];
    float* s_wt = sh;                       // H_*NL_ floats
    float* s_gb = s_wt + H_ * NL_;          // H_*2
    float* s_a  = s_gb + H_ * 2;            // 16*CSTR
    float* s_c  = s_a + 16 * CSTR;          // 16*CSTR

    const int tid = threadIdx.x;
    const int b  = blockIdx.z;
    const int i0 = blockIdx.x * 16;
    const int j0 = blockIdx.y * 16;
    const int ti = tid >> 4, tj = tid & 15;
    const int i = i0 + ti, j = j0 + tj;
    float* outp = out + ((size_t)(i * L_ + j) * B_ + b) * NL_;

    if (i0 > j0) {
        float4 z = make_float4(0.f, 0.f, 0.f, 0.f);
        float4* op4 = (float4*)outp;
        op4[0] = z; op4[1] = z; op4[2] = z; op4[3] = z;
        return;
    }

    for (int idx = tid; idx < H_ * NL_; idx += 256) {
        int n = idx / H_, h = idx - n * H_;
        s_wt[h * NL_ + n] = Wt[idx];
    }
    for (int h = tid; h < H_; h += 256) {
        s_gb[2 * h]     = gamma[h];
        s_gb[2 * h + 1] = beta[h];
    }

    const float inv = 1.0f / (float)H_;
    float mu, rstd;
    {
        float S0 = g_S[0][b][i], Q0 = g_Q[0][b][i], X0 = g_X[0][b][i];
        float S1 = g_S[1][b][j], Q1 = g_Q[1][b][j], X1 = g_X[1][b][j];
        float Uv = g_U0[b][i][j] + g_U1[b][i][j];
        float sum   = S0 + S1 + g_Sdd[b];
        float sumsq = Q0 + Q1 + g_Qdd[b] + 2.0f * (Uv + X0 + X1);
        mu = sum * inv;
        float var = fmaf(-mu, mu, sumsq * inv);
        rstd = rsqrtf(var + LN_EPS);
    }

    const int lr = tid >> 4;
    const int lq = tid & 15;
    const float* pa_base = g_a + (size_t)((i0 + lr) * B_ + b) * H_;
    const float* pc_base = g_c + (size_t)((j0 + lr) * B_ + b) * H_;
    const float* pd_base = g_dd + b * H_;

    unsigned long long acc[8];
    #pragma unroll
    for (int k = 0; k < 8; k++) acc[k] = 0ull;

    for (int ck = 0; ck < H_ / CHUNK; ck++) {
        int hb = ck * CHUNK + lq * 8;
        float4 a0 = *(const float4*)(pa_base + hb);
        float4 a1 = *(const float4*)(pa_base + hb + 4);
        float4 d0 = *(const float4*)(pd_base + hb);
        float4 d1 = *(const float4*)(pd_base + hb + 4);
        float4 c0 = *(const float4*)(pc_base + hb);
        float4 c1 = *(const float4*)(pc_base + hb + 4);
        __syncthreads();
        float* sa = &s_a[lr * CSTR + lq * 8];
        float* sc = &s_c[lr * CSTR + lq * 8];
        sa[0] = a0.x + d0.x; sa[1] = a0.y + d0.y; sa[2] = a0.z + d0.z; sa[3] = a0.w + d0.w;
        sa[4] = a1.x + d1.x; sa[5] = a1.y + d1.y; sa[6] = a1.z + d1.z; sa[7] = a1.w + d1.w;
        sc[0] = c0.x; sc[1] = c0.y; sc[2] = c0.z; sc[3] = c0.w;
        sc[4] = c1.x; sc[5] = c1.y; sc[6] = c1.z; sc[7] = c1.w;
        __syncthreads();
        const float* ra = &s_a[ti * CSTR];
        const float* rc = &s_c[tj * CSTR];
        #pragma unroll 4
        for (int hc = 0; hc < CHUNK; hc += 2) {
            int h = ck * CHUNK + hc;
            float2 pa = *(const float2*)&ra[hc];
            float2 pc = *(const float2*)&rc[hc];
            float4 gb = *(const float4*)&s_gb[2 * h];
            float x0 = fmaf((pa.x + pc.x - mu) * rstd, gb.x, gb.y);
            float x1 = fmaf((pa.y + pc.y - mu) * rstd, gb.z, gb.w);
            x0 = (x0 > 0.f) ? x0 : (__expf(x0) - 1.f);
            x1 = (x1 > 0.f) ? x1 : (__expf(x1) - 1.f);
            unsigned long long xx0 = pk2(x0, x0);
            unsigned long long xx1 = pk2(x1, x1);
            const ulonglong2* wp0 = (const ulonglong2*)&s_wt[h * NL_];
            const ulonglong2* wp1 = (const ulonglong2*)&s_wt[(h + 1) * NL_];
            ffma2(acc[0], xx0, wp0[0].x); ffma2(acc[1], xx0, wp0[0].y);
            ffma2(acc[2], xx0, wp0[1].x); ffma2(acc[3], xx0, wp0[1].y);
            ffma2(acc[4], xx0, wp0[2].x); ffma2(acc[5], xx0, wp0[2].y);
            ffma2(acc[6], xx0, wp0[3].x); ffma2(acc[7], xx0, wp0[3].y);
            ffma2(acc[0], xx1, wp1[0].x); ffma2(acc[1], xx1, wp1[0].y);
            ffma2(acc[2], xx1, wp1[1].x); ffma2(acc[3], xx1, wp1[1].y);
            ffma2(acc[4], xx1, wp1[2].x); ffma2(acc[5], xx1, wp1[2].y);
            ffma2(acc[6], xx1, wp1[3].x); ffma2(acc[7], xx1, wp1[3].y);
        }
    }

    float mval = (i <= j) ? mask[i * B_ + b] * mask[j * B_ + b] : 0.f;
    float res[16];
    #pragma unroll
    for (int k = 0; k < 8; k++) upk2(acc[k], res[2 * k], res[2 * k + 1]);
    #pragma unroll
    for (int n = 0; n < 16; n++) {
        float z = res[n] + bt[n];
        res[n] = mval * (1.0f / (1.0f + __expf(-z)));
    }
    float4* op4 = (float4*)outp;
    op4[0] = make_float4(res[0],  res[1],  res[2],  res[3]);
    op4[1] = make_float4(res[4],  res[5],  res[6],  res[7]);
    op4[2] = make_float4(res[8],  res[9],  res[10], res[11]);
    op4[3] = make_float4(res[12], res[13], res[14], res[15]);
}

// ---------------- launch ----------------
extern "C" void kernel_launch(void* const* d_in, const int* in_sizes, int n_in,
                              void* d_out, int out_size)
{
    const float* h_ner   = (const float*)d_in[0];
    const float* h_share = (const float*)d_in[1];
    const float* mask    = (const float*)d_in[2];
    const float* Wn      = (const float*)d_in[3];
    const float* bn      = (const float*)d_in[4];
    const float* W1      = (const float*)d_in[5];
    const float* b1      = (const float*)d_in[6];
    const float* gamma   = (const float*)d_in[7];
    const float* beta    = (const float*)d_in[8];
    const float* Wt      = (const float*)d_in[9];
    const float* bt      = (const float*)d_in[10];
    float* out = (float*)d_out;
    (void)in_sizes; (void)n_in; (void)out_size;

    gemm4_kernel<<<dim3(6, 6, 4), 256>>>(h_ner, h_share, Wn, W1);
    maxred_kernel<<<12, 256>>>(bn);
    dd_kernel<<<384, 256>>>(W1, b1);
    stats_kernel<<<L_ + 1, 256>>>();
    ugemm_kernel<<<dim3(3, 3, 8), 256>>>();

    const int smem_epi = (H_ * NL_ + H_ * 2 + 2 * 16 * CSTR) * (int)sizeof(float);
    cudaFuncSetAttribute(epilogue_kernel,
                         cudaFuncAttributeMaxDynamicSharedMemorySize, smem_epi);
    epilogue_kernel<<<dim3(12, 12, 4), 256, smem_epi>>>(mask, gamma, beta, Wt, bt, out);
}